// round 1
// baseline (speedup 1.0000x reference)
#include <cuda_runtime.h>
#include <math.h>

#define KF 16
#define TT 8
#define RRc 8
#define NN 32
#define NXc 64
#define NYc 64
#define NZc 32
#define VV (NXc*NYc*NZc)

__device__ unsigned int g_max_bits;

__device__ __forceinline__ unsigned long long pack2(float a, float b) {
    unsigned long long r;
    asm("mov.b64 %0, {%1,%2};" : "=l"(r) : "f"(a), "f"(b));
    return r;
}
__device__ __forceinline__ void unpack2(unsigned long long v, float& a, float& b) {
    asm("mov.b64 {%0,%1}, %2;" : "=f"(a), "=f"(b) : "l"(v));
}
__device__ __forceinline__ unsigned long long ffma2(unsigned long long a, unsigned long long b,
                                                    unsigned long long c) {
    unsigned long long d;
    asm("fma.rn.f32x2 %0, %1, %2, %3;" : "=l"(d) : "l"(a), "l"(b), "l"(c));
    return d;
}

extern "C" __global__ void kirch_init() {
    g_max_bits = 0u;
}

extern "C" __global__ void __launch_bounds__(128)
kirch_main(const float* __restrict__ freqs, const float* __restrict__ txp,
           const float* __restrict__ rxp, const float* __restrict__ xc,
           const float* __restrict__ yc, const float* __restrict__ zc,
           const float* __restrict__ yre, const float* __restrict__ yim,
           float* __restrict__ out)
{
    // smem: [n][kk*8 + r] float4 = (y_re, y_im, -y_im, y_re), one (t, k-half) chunk
    __shared__ float4 sy[NN * 64];
    __shared__ float2 skk[KF];   // (k_j, k_j^2)

    const int tid = threadIdx.x;
    if (tid < KF) {
        float kj = (float)(2.0 * M_PI / 299792458.0) * freqs[tid];
        skk[tid] = make_float2(kj, kj * kj);
    }

    const int v = blockIdx.x * 128 + tid;
    const int iz = v & 31;
    const int iy = (v >> 5) & 63;
    const int ix = v >> 11;
    const float px = xc[ix], py = yc[iy], pz = zc[iz];

    unsigned long long acc[NN];
#pragma unroll
    for (int n = 0; n < NN; n++) acc[n] = 0ull;

    const unsigned int sybase = (unsigned int)__cvta_generic_to_shared(sy);

    for (int t = 0; t < TT; t++) {
        const float dxt = px - txp[t * 3 + 0];
        const float dyt = py - txp[t * 3 + 1];
        const float dzt = pz - txp[t * 3 + 2];
        const float Rt = sqrtf(dxt * dxt + dyt * dyt + dzt * dzt);
        const float bt = dzt / Rt;

        for (int kh = 0; kh < 2; kh++) {
            __syncthreads();
            // stage y chunk: k in [kh*8, kh*8+8), all r, all n
            // e -> (r minor for coalesced global, m = kk*8+r consecutive in smem)
#pragma unroll
            for (int i = 0; i < 16; i++) {
                int e = i * 128 + tid;
                int r = e & 7;
                int kk = (e >> 3) & 7;
                int n = e >> 6;
                int gi = n * 1024 + (kh * 8 + kk) * 64 + t * 8 + r;
                float a = yre[gi];
                float b = yim[gi];
                sy[n * 64 + kk * 8 + r] = make_float4(a, b, -b, a);
            }
            __syncthreads();

            for (int r = 0; r < RRc; r++) {
                const float dxr = px - rxp[r * 3 + 0];
                const float dyr = py - rxp[r * 3 + 1];
                const float dzr = pz - rxp[r * 3 + 2];
                const float Rr = sqrtf(dxr * dxr + dyr * dyr + dzr * dzr);
                const float br = dzr / Rr;
                const float g = 4.0f * bt * br;
                const float Rs = Rt + Rr;
                const float q = g * Rt * Rr;     // g * Rprod
                const float gRs = g * Rs;

#pragma unroll 4
                for (int kk = 0; kk < 8; kk++) {
                    float2 kv = skk[kh * 8 + kk];
                    float ph = kv.x * Rs;
                    float s, c;
                    __sincosf(ph, &s, &c);
                    float are = fmaf(-q, kv.y, g);   // g * (1 - k^2 * Rprod)
                    float aim = gRs * kv.x;          // g * k * Rsum
                    float Are = are * c - aim * s;
                    float Aim = are * s + aim * c;
                    unsigned long long P1 = pack2(Are, Are);
                    unsigned long long P2 = pack2(Aim, Aim);
                    unsigned int addr = sybase + (unsigned int)((kk * 8 + r) * 16);
#pragma unroll
                    for (int n = 0; n < NN; n++) {
                        unsigned long long ypair, wpair;
                        asm("ld.shared.v2.b64 {%0,%1}, [%2];"
                            : "=l"(ypair), "=l"(wpair)
                            : "r"(addr + (unsigned int)(n * 1024)));
                        acc[n] = ffma2(P2, wpair, acc[n]);
                        acc[n] = ffma2(P1, ypair, acc[n]);
                    }
                }
            }
        }
    }

    // epilogue: magnitudes + global max
    float mx = 0.0f;
#pragma unroll
    for (int n = 0; n < NN; n++) {
        float re, im;
        unpack2(acc[n], re, im);
        float mag = sqrtf(re * re + im * im);
        out[n * VV + v] = mag;
        mx = fmaxf(mx, mag);
    }
#pragma unroll
    for (int o = 16; o > 0; o >>= 1)
        mx = fmaxf(mx, __shfl_xor_sync(0xffffffffu, mx, o));
    if ((tid & 31) == 0)
        atomicMax(&g_max_bits, __float_as_uint(mx));
}

extern "C" __global__ void kirch_norm(float* __restrict__ out) {
    const float mxv = __uint_as_float(g_max_bits);
    const float inv = 1.0f / mxv;
    int i = blockIdx.x * blockDim.x + threadIdx.x;
    const int total = NN * VV;
    const int stride = gridDim.x * blockDim.x;
    for (; i < total; i += stride) out[i] *= inv;
}

extern "C" void kernel_launch(void* const* d_in, const int* in_sizes, int n_in,
                              void* d_out, int out_size) {
    const float* freqs = (const float*)d_in[0];
    const float* txp   = (const float*)d_in[1];
    const float* rxp   = (const float*)d_in[2];
    const float* xc    = (const float*)d_in[3];
    const float* yc    = (const float*)d_in[4];
    const float* zc    = (const float*)d_in[5];
    const float* yre   = (const float*)d_in[6];
    const float* yim   = (const float*)d_in[7];
    float* out = (float*)d_out;

    kirch_init<<<1, 1>>>();
    kirch_main<<<VV / 128, 128>>>(freqs, txp, rxp, xc, yc, zc, yre, yim, out);
    kirch_norm<<<1024, 256>>>(out);
}

// round 3
// speedup vs baseline: 5.0068x; 5.0068x over previous
#include <cuda_runtime.h>
#include <cuda_fp16.h>
#include <math.h>
#include <stdint.h>

#define NN 32
#define VV 131072
#define NCHUNK 32
#define CTA_M 256

// smem: A tile [256 rows][128 B] at 0 (32 KB), B tile 8 KB at 32768. Total 40960.
// Epilogue reuses bytes [0, 33792) as float[64][132].
#define SMEM_TOTAL 40960

__device__ unsigned int g_max_bits;    // zero-init; reset by kirch_init each launch
__device__ __half g_W[NCHUNK * 4096];  // W pre-swizzled per-chunk [np 64][k 64] SW128 tiles

static __device__ __forceinline__ uint32_t smem_u32(const void* p) {
    uint32_t a;
    asm("{ .reg .u64 t; cvta.to.shared.u64 t, %1; cvt.u32.u64 %0, t; }" : "=r"(a) : "l"(p));
    return a;
}

#define STS128U(a0, a1, a2, a3, addr) \
    asm volatile("st.shared.v4.b32 [%0], {%1,%2,%3,%4};" \
                 :: "r"(addr), "r"(a0), "r"(a1), "r"(a2), "r"(a3) : "memory")

#define LDMX4(d0, d1, d2, d3, addr) \
    asm volatile("ldmatrix.sync.aligned.m8n8.x4.shared.b16 {%0,%1,%2,%3}, [%4];" \
                 : "=r"(d0), "=r"(d1), "=r"(d2), "=r"(d3) : "r"(addr))

#define MMA16816(c, a0, a1, a2, a3, b0, b1) \
    asm volatile("mma.sync.aligned.m16n8k16.row.col.f32.f16.f16.f32 " \
                 "{%0,%1,%2,%3}, {%4,%5,%6,%7}, {%8,%9}, {%0,%1,%2,%3};" \
                 : "+f"((c)[0]), "+f"((c)[1]), "+f"((c)[2]), "+f"((c)[3]) \
                 : "r"(a0), "r"(a1), "r"(a2), "r"(a3), "r"(b0), "r"(b1))

extern "C" __global__ void kirch_init() { g_max_bits = 0u; }

// Build W[64 n', 2048 m] fp16 laid out exactly as the per-chunk SW128 smem tile bytes.
// m = ((t*8+r)*16 + k)*2 + comp; rows n'<32 -> Re (yre, -yim), n'>=32 -> Im (yim, yre).
extern "C" __global__ void kirch_prep(const float* __restrict__ yre,
                                      const float* __restrict__ yim) {
    int e = blockIdx.x * 256 + threadIdx.x;   // 0..131071
    int np = e >> 11;                          // n' 0..63
    int m = e & 2047;
    int comp = m & 1;
    int mm = m >> 1;
    int k = mm & 15;
    int tr = mm >> 4;
    int t = tr >> 3, r = tr & 7;
    int n = np & 31;
    int part = np >> 5;
    int yi = n * 1024 + k * 64 + t * 8 + r;
    float v;
    if (part == 0) v = comp ? -yim[yi] : yre[yi];
    else           v = comp ?  yre[yi] : yim[yi];
    int chunk = m >> 6;
    int j = m & 63;
    unsigned off = (unsigned)(np * 128 + j * 2);
    unsigned sw = off ^ ((off >> 3) & 0x70);
    g_W[chunk * 4096 + (sw >> 1)] = __float2half_rn(v);
}

extern "C" __global__ void __launch_bounds__(256)
kirch_main(const float* __restrict__ freqs, const float* __restrict__ txp,
           const float* __restrict__ rxp, const float* __restrict__ xc,
           const float* __restrict__ yc, const float* __restrict__ zc,
           float* __restrict__ out)
{
    extern __shared__ unsigned char smem[];
    float* sfp = (float*)smem;
    const uint32_t sb = smem_u32(smem);
    const int tid = threadIdx.x;
    const int l = tid & 31;
    const int w = tid >> 5;

    const int v = blockIdx.x * CTA_M + tid;
    const int iz = v & 31;
    const int iy = (v >> 5) & 63;
    const int ix = v >> 11;
    const float px = xc[ix], py = yc[iy], pz = zc[iz];

    const float CC = (float)(2.0 * M_PI / 299792458.0);
    const float k0 = CC * freqs[0];
    const float dk = (CC * freqs[15] - k0) * (1.0f / 15.0f);

    float acc[64];   // [mt 2][nt 8][reg 4]
#pragma unroll
    for (int i = 0; i < 64; i++) acc[i] = 0.0f;

    // ldmatrix address components (constant across chunks)
    const uint32_t a_rb = sb + (uint32_t)((w * 32 + (l & 15)) * 128);  // + mt*2048
    const uint32_t b_rb = sb + 32768u + (uint32_t)((l & 15) * 128);    // + ng*2048
    const uint32_t sw7 = (uint32_t)(l & 7);
    const uint32_t u0 = (uint32_t)(l >> 4);
    const uint32_t rowoff = (uint32_t)(tid * 128);
    const uint32_t swx = (uint32_t)((tid & 7) << 4);

    for (int c = 0; c < NCHUNK; c++) {
        // stage B chunk (pre-swizzled): 8 KB, 512 float4 / 256 threads
        {
            const float4* src = (const float4*)(g_W + c * 4096);
            float4* dst = (float4*)(smem + 32768);
            dst[tid] = __ldg(src + tid);
            dst[256 + tid] = __ldg(src + 256 + tid);
        }

        // generate this thread's A row: 2 (t,r) pairs x 16 freqs
        const int t = c >> 2;
        const int r0 = (c & 3) << 1;
        const float dxt = px - txp[t * 3 + 0];
        const float dyt = py - txp[t * 3 + 1];
        const float dzt = pz - txp[t * 3 + 2];
        const float Rt = sqrtf(dxt * dxt + dyt * dyt + dzt * dzt);
        const float bt = dzt / Rt;

#pragma unroll
        for (int p = 0; p < 2; p++) {
            const int r = r0 + p;
            const float dxr = px - rxp[r * 3 + 0];
            const float dyr = py - rxp[r * 3 + 1];
            const float dzr = pz - rxp[r * 3 + 2];
            const float Rr = sqrtf(dxr * dxr + dyr * dyr + dzr * dzr);
            const float br = dzr / Rr;
            const float g = 0.03125f * bt * br;   // 4 * 2^-7; cancels in normalization
            const float Rs = Rt + Rr;
            const float qq = g * Rt * Rr;
            const float gRs = g * Rs;
            uint32_t q4[4];
#pragma unroll
            for (int k = 0; k < 16; k++) {
                float kj = fmaf((float)k, dk, k0);
                float ph = kj * Rs;
                float s, co;
                __sincosf(ph, &s, &co);
                float are = fmaf(-qq, kj * kj, g);
                float aim = gRs * kj;
                float t1 = aim * s;
                float t2 = aim * co;
                float Are = fmaf(are, co, -t1);
                float Aim = fmaf(are, s, t2);
                uint32_t hb;
                asm("cvt.rn.f16x2.f32 %0, %1, %2;" : "=r"(hb) : "f"(Aim), "f"(Are));
                q4[k & 3] = hb;
                if ((k & 3) == 3) {
                    uint32_t addr = sb + rowoff + ((uint32_t)((p << 6) + (k - 3) * 4) ^ swx);
                    STS128U(q4[0], q4[1], q4[2], q4[3], addr);
                }
            }
        }
        __syncthreads();

        // MMA: 4 k-steps of 16
#pragma unroll
        for (int ks = 0; ks < 4; ks++) {
            const uint32_t sx = (((u0 + (uint32_t)(ks * 2)) ^ sw7) << 4);
            uint32_t a0[4], a1[4];
            LDMX4(a0[0], a0[1], a0[2], a0[3], a_rb + sx);
            LDMX4(a1[0], a1[1], a1[2], a1[3], a_rb + 2048u + sx);
#pragma unroll
            for (int ng = 0; ng < 4; ng++) {
                uint32_t d0, d1, d2, d3;
                LDMX4(d0, d1, d2, d3, b_rb + (uint32_t)(ng * 2048) + sx);
                // lower n8 tile: {d0,d2}; upper: {d1,d3}
                MMA16816(&acc[(0 * 8 + ng * 2 + 0) * 4], a0[0], a0[1], a0[2], a0[3], d0, d2);
                MMA16816(&acc[(0 * 8 + ng * 2 + 1) * 4], a0[0], a0[1], a0[2], a0[3], d1, d3);
                MMA16816(&acc[(1 * 8 + ng * 2 + 0) * 4], a1[0], a1[1], a1[2], a1[3], d0, d2);
                MMA16816(&acc[(1 * 8 + ng * 2 + 1) * 4], a1[0], a1[1], a1[2], a1[3], d1, d3);
            }
        }
        __syncthreads();
    }

    // ---- epilogue: transpose through smem, coalesced magnitude stores, global max ----
    float mx = 0.0f;
    const int outbase = blockIdx.x * CTA_M;
#pragma unroll
    for (int phase = 0; phase < 2; phase++) {
        if ((w >> 2) == phase) {
#pragma unroll
            for (int mt = 0; mt < 2; mt++)
#pragma unroll
                for (int nt = 0; nt < 8; nt++)
#pragma unroll
                    for (int rg = 0; rg < 4; rg++) {
                        int np = nt * 8 + 2 * (l & 3) + (rg & 1);
                        int vl = ((w & 3) * 32) + mt * 16 + (l >> 2) + ((rg >> 1) << 3);
                        sfp[np * 132 + vl] = acc[(mt * 8 + nt) * 4 + rg];
                    }
        }
        __syncthreads();
#pragma unroll
        for (int it = 0; it < 16; it++) {
            int idx = tid + it * 256;
            int n = idx >> 7;
            int vl = idx & 127;
            float re = sfp[n * 132 + vl];
            float im = sfp[(n + 32) * 132 + vl];
            float mag = sqrtf(re * re + im * im);
            out[n * VV + outbase + phase * 128 + vl] = mag;
            mx = fmaxf(mx, mag);
        }
        __syncthreads();
    }
#pragma unroll
    for (int o = 16; o > 0; o >>= 1)
        mx = fmaxf(mx, __shfl_xor_sync(0xffffffffu, mx, o));
    if (l == 0) atomicMax(&g_max_bits, __float_as_uint(mx));
}

extern "C" __global__ void kirch_norm(float* __restrict__ out) {
    const float inv = 1.0f / __uint_as_float(g_max_bits);
    int i = blockIdx.x * blockDim.x + threadIdx.x;
    const int total = NN * VV;
    const int stride = gridDim.x * blockDim.x;
    for (; i < total; i += stride) out[i] *= inv;
}

extern "C" void kernel_launch(void* const* d_in, const int* in_sizes, int n_in,
                              void* d_out, int out_size) {
    const float* freqs = (const float*)d_in[0];
    const float* txp   = (const float*)d_in[1];
    const float* rxp   = (const float*)d_in[2];
    const float* xc    = (const float*)d_in[3];
    const float* yc    = (const float*)d_in[4];
    const float* zc    = (const float*)d_in[5];
    const float* yre   = (const float*)d_in[6];
    const float* yim   = (const float*)d_in[7];
    float* out = (float*)d_out;

    cudaFuncSetAttribute(kirch_main, cudaFuncAttributeMaxDynamicSharedMemorySize, SMEM_TOTAL);

    kirch_init<<<1, 1>>>();
    kirch_prep<<<512, 256>>>(yre, yim);
    kirch_main<<<VV / CTA_M, CTA_M, SMEM_TOTAL>>>(freqs, txp, rxp, xc, yc, zc, out);
    kirch_norm<<<1024, 256>>>(out);
}